// round 13
// baseline (speedup 1.0000x reference)
#include <cuda_runtime.h>
#include <cstdint>

// Problem constants
#define B      128
#define CMAX   1024
#define DIN    1024
#define KTOT   2048          // 2 * DIN (complement coding)
#define NC     10
#define ALPHA  1e-3f
#define GAMMA  1e-2f

// choice kernel tiling
#define CT     8             // categories per block -> grid 128
#define KSLICE 128           // k per warp (16 warps cover 2048)
#define NITER  32            // KSLICE / 4

// -------- scratch (device globals; no allocation allowed) --------
__device__ float g_codedT[(KTOT + 4) * B];   // transposed [k][b], +4 pad rows for x prefetch overrun
__device__ float g_choice[B * CMAX];
__device__ float g_pmn[128];
__device__ float g_pmx[128];

// ---------------- 1. per-block min/max partials ----------------
__global__ void mm_part_kernel(const float* __restrict__ x) {
    int tid = threadIdx.x;                       // 256 threads
    const float* p = x + blockIdx.x * 1024;      // 128 blocks * 1024 elems
    float mn = 3.402823466e38f, mx = -3.402823466e38f;
#pragma unroll
    for (int i = 0; i < 4; i++) {
        float v = p[tid + i * 256];
        mn = fminf(mn, v);
        mx = fmaxf(mx, v);
    }
#pragma unroll
    for (int o = 16; o; o >>= 1) {
        mn = fminf(mn, __shfl_xor_sync(0xffffffffu, mn, o));
        mx = fmaxf(mx, __shfl_xor_sync(0xffffffffu, mx, o));
    }
    __shared__ float smn[8], smx[8];
    if ((tid & 31) == 0) { smn[tid >> 5] = mn; smx[tid >> 5] = mx; }
    __syncthreads();
    if (tid == 0) {
        mn = smn[0]; mx = smx[0];
#pragma unroll
        for (int w = 1; w < 8; w++) { mn = fminf(mn, smn[w]); mx = fmaxf(mx, smx[w]); }
        g_pmn[blockIdx.x] = mn;
        g_pmx[blockIdx.x] = mx;
    }
}

// ---------------- 2. normalize + complement-code + transpose ----------------
__global__ void codedT_kernel(const float* __restrict__ x) {
    __shared__ float sT[16][129];
    __shared__ float rmn[8], rmx[8];
    __shared__ float s_mn, s_inv;
    int tid = threadIdx.x;                       // 256 threads

    {
        float mn = 3.402823466e38f, mx = -3.402823466e38f;
        if (tid < 128) { mn = g_pmn[tid]; mx = g_pmx[tid]; }
#pragma unroll
        for (int o = 16; o; o >>= 1) {
            mn = fminf(mn, __shfl_xor_sync(0xffffffffu, mn, o));
            mx = fmaxf(mx, __shfl_xor_sync(0xffffffffu, mx, o));
        }
        if ((tid & 31) == 0) { rmn[tid >> 5] = mn; rmx[tid >> 5] = mx; }
    }
    int d0 = blockIdx.x * 16;
#pragma unroll
    for (int p = 0; p < 8; p++) {
        int idx = tid + p * 256;                 // 0..2047
        int b = idx >> 4, dd = idx & 15;
        sT[dd][b] = x[b * 1024 + d0 + dd];
    }
    __syncthreads();
    if (tid == 0) {
        float mn = fminf(fminf(rmn[0], rmn[1]), fminf(rmn[2], rmn[3]));
        float mx = fmaxf(fmaxf(rmx[0], rmx[1]), fmaxf(rmx[2], rmx[3]));
        s_mn = mn;
        s_inv = 1.0f / (mx - mn + 1e-10f);
    }
    __syncthreads();
    float mn = s_mn, inv = s_inv;
#pragma unroll
    for (int p = 0; p < 8; p++) {
        int q = tid + p * 256;
        int dd = q >> 7, b = q & 127;
        float v = (sT[dd][b] - mn) * inv;
        g_codedT[(d0 + dd) * 128 + b] = v;
        g_codedT[(1024 + d0 + dd) * 128 + b] = 1.0f - v;
    }
}

// ---------------- 3. choice matrix + fused denominator (fp32) ----------------
#define CP_ASYNC16(dst_u32, src_ptr) \
    asm volatile("cp.async.ca.shared.global [%0], [%1], 16;" \
                 :: "r"(dst_u32), "l"(src_ptr) : "memory")
#define CP_COMMIT()  asm volatile("cp.async.commit_group;" ::: "memory")
#define CP_WAIT2()   asm volatile("cp.async.wait_group 2;" ::: "memory")

#define MATH_BODY(XX, TST)                                                                 \
    _Pragma("unroll")                                                                      \
    for (int s = 0; s < 8; s++) {                                                          \
        float4 tf = (TST)[s];                                                              \
        float a0 = fminf(XX[0].x, tf.x), a1 = fminf(XX[1].x, tf.y);                        \
        float a2 = fminf(XX[2].x, tf.z), a3 = fminf(XX[3].x, tf.w);                        \
        acc[0][s] += (a0 + a1) + (a2 + a3);                                                \
        float b0 = fminf(XX[0].y, tf.x), b1 = fminf(XX[1].y, tf.y);                        \
        float b2 = fminf(XX[2].y, tf.z), b3 = fminf(XX[3].y, tf.w);                        \
        acc[1][s] += (b0 + b1) + (b2 + b3);                                                \
        float c0 = fminf(XX[0].z, tf.x), c1 = fminf(XX[1].z, tf.y);                        \
        float c2 = fminf(XX[2].z, tf.z), c3 = fminf(XX[3].z, tf.w);                        \
        acc[2][s] += (c0 + c1) + (c2 + c3);                                                \
        float e0 = fminf(XX[0].w, tf.x), e1 = fminf(XX[1].w, tf.y);                        \
        float e2 = fminf(XX[2].w, tf.z), e3 = fminf(XX[3].w, tf.w);                        \
        acc[3][s] += (e0 + e1) + (e2 + e3);                                                \
        ulonglong2 tu = ((const ulonglong2*)(TST))[s];                                     \
        asm volatile("add.rn.f32x2 %0, %0, %1;" : "+l"(ts2[s]) : "l"(tu.x));               \
        asm volatile("add.rn.f32x2 %0, %0, %1;" : "+l"(ts2[s]) : "l"(tu.y));               \
    }

__global__ __launch_bounds__(512)
void choice_kernel(const float* __restrict__ templates,
                   const int* __restrict__ counts) {
    __shared__ __align__(16) float stg[16 * 128];      // 8 KB: per-warp 4-stage ring
    __shared__ float sacc[8][128][9];                  // 36.9 KB (stride-9 pad)
    __shared__ float stsum[16][8];
    __shared__ float sden[8];

    int tid = threadIdx.x, w = tid >> 5, l = tid & 31;
    int cbase = blockIdx.x * CT;
    int kbase = w * KSLICE;

    float* mystg = stg + w * 128;                 // 4 stages x 32 floats
    uint32_t stg_u32 = (uint32_t)__cvta_generic_to_shared(mystg);

    const float4* xp = (const float4*)g_codedT;   // row = 32 float4s
    const float* tl = templates + (size_t)(cbase + (l & 7)) * KTOT + kbase;

    float acc[4][8];
    unsigned long long ts2[8];
#pragma unroll
    for (int r = 0; r < 4; r++)
#pragma unroll
        for (int s = 0; s < 8; s++) acc[r][s] = 0.f;
#pragma unroll
    for (int s = 0; s < 8; s++) ts2[s] = 0ull;

    // prologue: stage t(0), t(1), t(2)
#pragma unroll
    for (int p = 0; p < 3; p++) {
        if (l < 8) CP_ASYNC16(stg_u32 + (p & 3) * 128 + l * 16, tl + p * 4);
        CP_COMMIT();
    }
    float4 x0[4], x1[4];
#pragma unroll
    for (int j = 0; j < 4; j++) x0[j] = xp[(kbase + j) * 32 + l];

#pragma unroll 1
    for (int i = 0; i < NITER; i += 2) {
        // ---- consume iter i (x0); x prefetch issued before the wait ----
#pragma unroll
        for (int j = 0; j < 4; j++) x1[j] = xp[(kbase + 4 * (i + 1) + j) * 32 + l];
        CP_WAIT2();
        __syncwarp();
        if (l < 8 && i < NITER - 3)
            CP_ASYNC16(stg_u32 + ((i + 3) & 3) * 128 + l * 16, tl + (i + 3) * 4);
        CP_COMMIT();
        {
            const float4* tst = (const float4*)(mystg + (i & 3) * 32);
            MATH_BODY(x0, tst)
        }
        // ---- consume iter i+1 (x1) ----
#pragma unroll
        for (int j = 0; j < 4; j++) x0[j] = xp[(kbase + 4 * (i + 2) + j) * 32 + l];  // pad rows cover i=30
        CP_WAIT2();
        __syncwarp();
        if (l < 8 && i + 1 < NITER - 3)
            CP_ASYNC16(stg_u32 + ((i + 4) & 3) * 128 + l * 16, tl + (i + 4) * 4);
        CP_COMMIT();
        {
            const float4* tst = (const float4*)(mystg + ((i + 1) & 3) * 32);
            MATH_BODY(x1, tst)
        }
    }

    // ---- per-warp template sums ----
    if (l == 0) {
#pragma unroll
        for (int s = 0; s < 8; s++) {
            float lo = __uint_as_float((unsigned)(ts2[s] & 0xffffffffull));
            float hi = __uint_as_float((unsigned)(ts2[s] >> 32));
            stsum[w][s] = lo + hi;
        }
    }

    // ---- staged cross-warp (k-split) reduction: 16 warps -> 8 slices -> 1 ----
    int half = w >> 1;
    if ((w & 1) == 0) {
#pragma unroll
        for (int r = 0; r < 4; r++) {
            int b = 4 * l + r;
#pragma unroll
            for (int s = 0; s < 8; s++) sacc[half][b][s] = acc[r][s];
        }
    }
    __syncthreads();
    if (w & 1) {
#pragma unroll
        for (int r = 0; r < 4; r++) {
            int b = 4 * l + r;
#pragma unroll
            for (int s = 0; s < 8; s++) sacc[half][b][s] += acc[r][s];
        }
    }
    __syncthreads();
    if (tid < 8) {
        float ssum = 0.f;
#pragma unroll
        for (int ww = 0; ww < 16; ww++) ssum += stsum[ww][tid];
        sden[tid] = ALPHA + ssum + GAMMA * (float)counts[cbase + tid];
    }
    __syncthreads();
#pragma unroll
    for (int p = tid; p < 1024; p += 512) {
        int b = p >> 3, s = p & 7;
        float v = 0.f;
#pragma unroll
        for (int hh = 0; hh < 8; hh++) v += sacc[hh][b][s];
        g_choice[b * CMAX + cbase + s] = v / sden[s];
    }
}

// ---------------- 4. finalize: argmax, then ONE predicated sum (one-hot output) ----------------
__global__ void __launch_bounds__(256) finalize_kernel(const int* __restrict__ committed,
                                                       const int* __restrict__ labels,
                                                       float* __restrict__ out) {
    __shared__ unsigned long long s_best[8];
    __shared__ float s_sum[8];
    __shared__ int s_plab;

    int b = blockIdx.x;
    int tid = threadIdx.x, w = tid >> 5;

    float vz[4];
    int   lab[4];
    unsigned long long packed = 0ull;
#pragma unroll
    for (int i = 0; i < 4; i++) {
        int c = tid + i * 256;
        float v = g_choice[b * CMAX + c];
        bool com = committed[c] != 0;
        lab[i] = labels[c];
        vz[i] = com ? v : 0.f;
        // key: value bits high (nonneg fp32 -> monotonic), ~c low (first-index tie-break)
        unsigned long long p = com
            ? (((unsigned long long)__float_as_uint(v)) << 32) | (unsigned)(~c)
            : 0ull;
        if (p > packed) packed = p;
    }
#pragma unroll
    for (int o = 16; o; o >>= 1) {
        unsigned long long op = __shfl_xor_sync(0xffffffffu, packed, o);
        if (op > packed) packed = op;
    }
    if ((tid & 31) == 0) s_best[w] = packed;
    __syncthreads();
    if (tid == 0) {
        unsigned long long best = s_best[0];
#pragma unroll
        for (int ww = 1; ww < 8; ww++) if (s_best[ww] > best) best = s_best[ww];
        int idx = (int)((~(unsigned)best) & (CMAX - 1));
        s_plab = labels[idx];
    }
    __syncthreads();

    int plab = s_plab;
    float sum = 0.f;
#pragma unroll
    for (int i = 0; i < 4; i++)
        sum += (lab[i] == plab) ? vz[i] : 0.f;
#pragma unroll
    for (int o = 16; o; o >>= 1)
        sum += __shfl_xor_sync(0xffffffffu, sum, o);
    if ((tid & 31) == 0) s_sum[w] = sum;
    __syncthreads();

    if (tid < NC) {
        float tot = s_sum[0] + s_sum[1] + s_sum[2] + s_sum[3]
                  + s_sum[4] + s_sum[5] + s_sum[6] + s_sum[7];
        out[b * NC + tid] = (tid == plab) ? tot : 0.f;
    }
}

// ---------------- launch ----------------
extern "C" void kernel_launch(void* const* d_in, const int* in_sizes, int n_in,
                              void* d_out, int out_size) {
    const float* x         = (const float*)d_in[0];
    const float* templates = (const float*)d_in[1];
    const int*   committed = (const int*)d_in[2];     // bool -> int32
    const int*   labels    = (const int*)d_in[3];
    const int*   counts    = (const int*)d_in[4];
    float*       out       = (float*)d_out;

    mm_part_kernel<<<128, 256>>>(x);
    codedT_kernel<<<64, 256>>>(x);
    choice_kernel<<<CMAX / CT, 512>>>(templates, counts);
    finalize_kernel<<<B, 256>>>(committed, labels, out);
}

// round 15
// speedup vs baseline: 1.0508x; 1.0508x over previous
#include <cuda_runtime.h>
#include <cstdint>

// Problem constants
#define B      128
#define CMAX   1024
#define DIN    1024
#define KTOT   2048          // 2 * DIN (complement coding)
#define NC     10
#define ALPHA  1e-3f
#define GAMMA  1e-2f

// choice kernel tiling
#define CT     8             // categories per block -> grid 128
#define KSLICE 128           // k per warp (16 warps cover 2048)
#define NITER  32            // KSLICE / 4

// -------- scratch (device globals; no allocation allowed) --------
__device__ float g_codedT[(KTOT + 4) * B];   // transposed [k][b], +4 pad rows for x prefetch overrun
__device__ float g_choice[B * CMAX];
__device__ float g_pmn[128];
__device__ float g_pmx[128];
__device__ unsigned g_arrive;                // grid-barrier counter (zeroed each replay by mm_part)

// ---------------- 1. per-block min/max partials (+ barrier reset) ----------------
__global__ void mm_part_kernel(const float* __restrict__ x) {
    int tid = threadIdx.x;                       // 256 threads
    if (blockIdx.x == 0 && tid == 0) g_arrive = 0u;   // reset for this graph replay

    const float* p = x + blockIdx.x * 1024;      // 128 blocks * 1024 elems
    float mn = 3.402823466e38f, mx = -3.402823466e38f;
#pragma unroll
    for (int i = 0; i < 4; i++) {
        float v = p[tid + i * 256];
        mn = fminf(mn, v);
        mx = fmaxf(mx, v);
    }
#pragma unroll
    for (int o = 16; o; o >>= 1) {
        mn = fminf(mn, __shfl_xor_sync(0xffffffffu, mn, o));
        mx = fmaxf(mx, __shfl_xor_sync(0xffffffffu, mx, o));
    }
    __shared__ float smn[8], smx[8];
    if ((tid & 31) == 0) { smn[tid >> 5] = mn; smx[tid >> 5] = mx; }
    __syncthreads();
    if (tid == 0) {
        mn = smn[0]; mx = smx[0];
#pragma unroll
        for (int w = 1; w < 8; w++) { mn = fminf(mn, smn[w]); mx = fmaxf(mx, smx[w]); }
        g_pmn[blockIdx.x] = mn;
        g_pmx[blockIdx.x] = mx;
    }
}

// ---------------- 2. normalize + complement-code + transpose ----------------
__global__ void codedT_kernel(const float* __restrict__ x) {
    __shared__ float sT[16][129];
    __shared__ float rmn[8], rmx[8];
    __shared__ float s_mn, s_inv;
    int tid = threadIdx.x;                       // 256 threads

    {
        float mn = 3.402823466e38f, mx = -3.402823466e38f;
        if (tid < 128) { mn = g_pmn[tid]; mx = g_pmx[tid]; }
#pragma unroll
        for (int o = 16; o; o >>= 1) {
            mn = fminf(mn, __shfl_xor_sync(0xffffffffu, mn, o));
            mx = fmaxf(mx, __shfl_xor_sync(0xffffffffu, mx, o));
        }
        if ((tid & 31) == 0) { rmn[tid >> 5] = mn; rmx[tid >> 5] = mx; }
    }
    int d0 = blockIdx.x * 16;
#pragma unroll
    for (int p = 0; p < 8; p++) {
        int idx = tid + p * 256;                 // 0..2047
        int b = idx >> 4, dd = idx & 15;
        sT[dd][b] = x[b * 1024 + d0 + dd];
    }
    __syncthreads();
    if (tid == 0) {
        float mn = fminf(fminf(rmn[0], rmn[1]), fminf(rmn[2], rmn[3]));
        float mx = fmaxf(fmaxf(rmx[0], rmx[1]), fmaxf(rmx[2], rmx[3]));
        s_mn = mn;
        s_inv = 1.0f / (mx - mn + 1e-10f);
    }
    __syncthreads();
    float mn = s_mn, inv = s_inv;
#pragma unroll
    for (int p = 0; p < 8; p++) {
        int q = tid + p * 256;
        int dd = q >> 7, b = q & 127;
        float v = (sT[dd][b] - mn) * inv;
        g_codedT[(d0 + dd) * 128 + b] = v;
        g_codedT[(1024 + d0 + dd) * 128 + b] = 1.0f - v;
    }
}

// ---------------- 3. choice + denom + (grid barrier) + finalize, all fused ----------------
#define CP_ASYNC16(dst_u32, src_ptr) \
    asm volatile("cp.async.ca.shared.global [%0], [%1], 16;" \
                 :: "r"(dst_u32), "l"(src_ptr) : "memory")
#define CP_COMMIT()  asm volatile("cp.async.commit_group;" ::: "memory")
#define CP_WAIT2()   asm volatile("cp.async.wait_group 2;" ::: "memory")

#define MATH_BODY(XX, TST)                                                                 \
    _Pragma("unroll")                                                                      \
    for (int s = 0; s < 8; s++) {                                                          \
        float4 tf = (TST)[s];                                                              \
        float a0 = fminf(XX[0].x, tf.x), a1 = fminf(XX[1].x, tf.y);                        \
        float a2 = fminf(XX[2].x, tf.z), a3 = fminf(XX[3].x, tf.w);                        \
        acc[0][s] += (a0 + a1) + (a2 + a3);                                                \
        float b0 = fminf(XX[0].y, tf.x), b1 = fminf(XX[1].y, tf.y);                        \
        float b2 = fminf(XX[2].y, tf.z), b3 = fminf(XX[3].y, tf.w);                        \
        acc[1][s] += (b0 + b1) + (b2 + b3);                                                \
        float c0 = fminf(XX[0].z, tf.x), c1 = fminf(XX[1].z, tf.y);                        \
        float c2 = fminf(XX[2].z, tf.z), c3 = fminf(XX[3].z, tf.w);                        \
        acc[2][s] += (c0 + c1) + (c2 + c3);                                                \
        float e0 = fminf(XX[0].w, tf.x), e1 = fminf(XX[1].w, tf.y);                        \
        float e2 = fminf(XX[2].w, tf.z), e3 = fminf(XX[3].w, tf.w);                        \
        acc[3][s] += (e0 + e1) + (e2 + e3);                                                \
        ulonglong2 tu = ((const ulonglong2*)(TST))[s];                                     \
        asm volatile("add.rn.f32x2 %0, %0, %1;" : "+l"(ts2[s]) : "l"(tu.x));               \
        asm volatile("add.rn.f32x2 %0, %0, %1;" : "+l"(ts2[s]) : "l"(tu.y));               \
    }

__global__ __launch_bounds__(512)
void choice_kernel(const float* __restrict__ templates,
                   const int* __restrict__ counts,
                   const int* __restrict__ committed,
                   const int* __restrict__ labels,
                   float* __restrict__ out) {
    __shared__ __align__(16) float stg[16 * 128];      // 8 KB: per-warp 4-stage ring
    __shared__ float sacc[8][128][9];                  // 36.9 KB (stride-9 pad)
    __shared__ float stsum[16][8];
    __shared__ float sden[8];
    __shared__ unsigned long long s_best[16];
    __shared__ float s_sum[16];
    __shared__ int s_plab;

    int tid = threadIdx.x, w = tid >> 5, l = tid & 31;
    int cbase = blockIdx.x * CT;
    int kbase = w * KSLICE;

    float* mystg = stg + w * 128;                 // 4 stages x 32 floats
    uint32_t stg_u32 = (uint32_t)__cvta_generic_to_shared(mystg);

    const float4* xp = (const float4*)g_codedT;   // row = 32 float4s
    const float* tl = templates + (size_t)(cbase + (l & 7)) * KTOT + kbase;

    float acc[4][8];
    unsigned long long ts2[8];
#pragma unroll
    for (int r = 0; r < 4; r++)
#pragma unroll
        for (int s = 0; s < 8; s++) acc[r][s] = 0.f;
#pragma unroll
    for (int s = 0; s < 8; s++) ts2[s] = 0ull;

    // prologue: stage t(0), t(1), t(2)
#pragma unroll
    for (int p = 0; p < 3; p++) {
        if (l < 8) CP_ASYNC16(stg_u32 + (p & 3) * 128 + l * 16, tl + p * 4);
        CP_COMMIT();
    }
    float4 x0[4], x1[4];
#pragma unroll
    for (int j = 0; j < 4; j++) x0[j] = xp[(kbase + j) * 32 + l];

#pragma unroll 1
    for (int i = 0; i < NITER; i += 2) {
        // ---- consume iter i (x0) ----  (R4-proven ordering: x loads after the wait)
        CP_WAIT2();
        __syncwarp();
        if (l < 8 && i < NITER - 3)
            CP_ASYNC16(stg_u32 + ((i + 3) & 3) * 128 + l * 16, tl + (i + 3) * 4);
        CP_COMMIT();
#pragma unroll
        for (int j = 0; j < 4; j++) x1[j] = xp[(kbase + 4 * (i + 1) + j) * 32 + l];
        {
            const float4* tst = (const float4*)(mystg + (i & 3) * 32);
            MATH_BODY(x0, tst)
        }
        // ---- consume iter i+1 (x1) ----
        CP_WAIT2();
        __syncwarp();
        if (l < 8 && i + 1 < NITER - 3)
            CP_ASYNC16(stg_u32 + ((i + 4) & 3) * 128 + l * 16, tl + (i + 4) * 4);
        CP_COMMIT();
#pragma unroll
        for (int j = 0; j < 4; j++) x0[j] = xp[(kbase + 4 * (i + 2) + j) * 32 + l];  // pad rows cover i=30
        {
            const float4* tst = (const float4*)(mystg + ((i + 1) & 3) * 32);
            MATH_BODY(x1, tst)
        }
    }

    // ---- per-warp template sums ----
    if (l == 0) {
#pragma unroll
        for (int s = 0; s < 8; s++) {
            float lo = __uint_as_float((unsigned)(ts2[s] & 0xffffffffull));
            float hi = __uint_as_float((unsigned)(ts2[s] >> 32));
            stsum[w][s] = lo + hi;
        }
    }

    // ---- staged cross-warp (k-split) reduction: 16 warps -> 8 slices -> 1 ----
    int half = w >> 1;
    if ((w & 1) == 0) {
#pragma unroll
        for (int r = 0; r < 4; r++) {
            int b = 4 * l + r;
#pragma unroll
            for (int s = 0; s < 8; s++) sacc[half][b][s] = acc[r][s];
        }
    }
    __syncthreads();
    if (w & 1) {
#pragma unroll
        for (int r = 0; r < 4; r++) {
            int b = 4 * l + r;
#pragma unroll
            for (int s = 0; s < 8; s++) sacc[half][b][s] += acc[r][s];
        }
    }
    __syncthreads();
    if (tid < 8) {
        float ssum = 0.f;
#pragma unroll
        for (int ww = 0; ww < 16; ww++) ssum += stsum[ww][tid];
        sden[tid] = ALPHA + ssum + GAMMA * (float)counts[cbase + tid];
    }
    __syncthreads();
#pragma unroll
    for (int p = tid; p < 1024; p += 512) {
        int b = p >> 3, s = p & 7;
        float v = 0.f;
#pragma unroll
        for (int hh = 0; hh < 8; hh++) v += sacc[hh][b][s];
        g_choice[b * CMAX + cbase + s] = v / sden[s];
    }

    // ================= grid barrier (all 128 blocks co-resident: 128 <= 148 SMs) =================
    __syncthreads();                              // all g_choice stores issued
    if (tid == 0) {
        __threadfence();                          // publish g_choice before arriving
        atomicAdd(&g_arrive, 1u);
        while (atomicAdd(&g_arrive, 0u) < 128u) {}  // spin until every block arrived
        __threadfence();                          // order spin before the reads below
    }
    __syncthreads();

    // ================= fused finalize: block handles batch row b = blockIdx.x =================
    {
        int b = blockIdx.x;
        int c0 = tid, c1 = tid + 512;
        float v0 = g_choice[b * CMAX + c0];
        float v1 = g_choice[b * CMAX + c1];
        bool m0 = committed[c0] != 0, m1 = committed[c1] != 0;
        int lab0 = labels[c0], lab1 = labels[c1];
        float vz0 = m0 ? v0 : 0.f, vz1 = m1 ? v1 : 0.f;

        // packed key: value bits high (nonneg fp32 -> monotonic), ~c low (first-index tie-break)
        unsigned long long p0 = m0
            ? (((unsigned long long)__float_as_uint(v0)) << 32) | (unsigned)(~c0) : 0ull;
        unsigned long long p1 = m1
            ? (((unsigned long long)__float_as_uint(v1)) << 32) | (unsigned)(~c1) : 0ull;
        unsigned long long packed = (p1 > p0) ? p1 : p0;
#pragma unroll
        for (int o = 16; o; o >>= 1) {
            unsigned long long op = __shfl_xor_sync(0xffffffffu, packed, o);
            if (op > packed) packed = op;
        }
        if (l == 0) s_best[w] = packed;
        __syncthreads();
        if (tid == 0) {
            unsigned long long best = s_best[0];
#pragma unroll
            for (int ww = 1; ww < 16; ww++) if (s_best[ww] > best) best = s_best[ww];
            int idx = (int)((~(unsigned)best) & (CMAX - 1));
            s_plab = labels[idx];
        }
        __syncthreads();

        int plab = s_plab;
        float sum = ((lab0 == plab) ? vz0 : 0.f) + ((lab1 == plab) ? vz1 : 0.f);
#pragma unroll
        for (int o = 16; o; o >>= 1)
            sum += __shfl_xor_sync(0xffffffffu, sum, o);
        if (l == 0) s_sum[w] = sum;
        __syncthreads();

        if (tid < NC) {
            float tot = 0.f;
#pragma unroll
            for (int ww = 0; ww < 16; ww++) tot += s_sum[ww];
            out[b * NC + tid] = (tid == plab) ? tot : 0.f;
        }
    }
}

// ---------------- launch ----------------
extern "C" void kernel_launch(void* const* d_in, const int* in_sizes, int n_in,
                              void* d_out, int out_size) {
    const float* x         = (const float*)d_in[0];
    const float* templates = (const float*)d_in[1];
    const int*   committed = (const int*)d_in[2];     // bool -> int32
    const int*   labels    = (const int*)d_in[3];
    const int*   counts    = (const int*)d_in[4];
    float*       out       = (float*)d_out;

    mm_part_kernel<<<128, 256>>>(x);
    codedT_kernel<<<64, 256>>>(x);
    choice_kernel<<<CMAX / CT, 512>>>(templates, counts, committed, labels, out);
}